// round 5
// baseline (speedup 1.0000x reference)
#include <cuda_runtime.h>
#include <cstdint>

typedef unsigned long long ull;

#define RB 7
#define WARPS 8
#define PAIRS 4
#define NTHR (WARPS*32)
#define EPC (PAIRS*RB)   // 28
#define BB 4096
#define TT 2048

// smem float offsets
#define OFF_WP 0                 // [100 k][7 s][64 = 2*lane+half] -> 44800 floats
#define OFF_BI 44800             // [7][64]
#define OFF_WX 45248             // [7][64]
#define OFF_HD 45696             // [PAIRS][RB][100] ull -> 4*7*100*2 = 5600 floats
#define SMEM_FLOATS (45696 + 5600)
#define SMEM_BYTES (SMEM_FLOATS*4)

__device__ __forceinline__ ull pk2(float lo, float hi) {
    ull r; asm("mov.b64 %0, {%1, %2};" : "=l"(r) : "f"(lo), "f"(hi)); return r;
}
__device__ __forceinline__ void upk2(ull v, float& lo, float& hi) {
    asm("mov.b64 {%0, %1}, %2;" : "=f"(lo), "=f"(hi) : "l"(v));
}
__device__ __forceinline__ ull fma2(ull a, ull b, ull c) {
    ull d; asm("fma.rn.f32x2 %0, %1, %2, %3;" : "=l"(d) : "l"(a), "l"(b), "l"(c)); return d;
}
__device__ __forceinline__ float sigf(float x) {
    float e = __expf(-x);
    return __fdividef(1.0f, 1.0f + e);
}
__device__ __forceinline__ float tahf(float x) {
    float a = fabsf(x);
    float E = __expf(2.0f * a);
    float t = 1.0f - __fdividef(2.0f, E + 1.0f);
    return (x < 0.0f) ? -t : t;
}
__device__ __forceinline__ float xor1(float v) {
    return __shfl_xor_sync(0xffffffffu, v, 1);
}
__device__ __forceinline__ void barp(int id) {
    asm volatile("bar.sync %0, %1;" :: "r"(id), "r"(64) : "memory");
}

// HALF 0: slots {0,1,2,6}  (units 0..47 and 96..99)
// HALF 1: slots {3,4,5}    (units 48..95) + layer-2 + output
template<int HALF>
__device__ __forceinline__ void time_loop(
    const float* __restrict__ input, float* __restrict__ out,
    const float* sWP, const float* sBI, const float* sWX, ull* hd,
    int lane, int pair, int base_elem,
    const float* __restrict__ W_ih2, const float* __restrict__ W_hh2,
    const float* __restrict__ b_ih2, const float* __restrict__ b_hh2)
{
    constexpr int NS = HALF ? 3 : 4;
    constexpr int SL[4] = { HALF ? 3 : 0, HALF ? 4 : 1, HALF ? 5 : 2, HALF ? 5 : 6 };
    const int preid  = 1 + pair;   // ids 1..4
    const int postid = 5 + pair;   // ids 5..8

    // cached per-lane weight constants for own slots
    ull wxr[NS], bbr[NS];
    #pragma unroll
    for (int i = 0; i < NS; ++i) {
        wxr[i] = *reinterpret_cast<const ull*>(sWX + SL[i]*64 + 2*lane);
        bbr[i] = *reinterpret_cast<const ull*>(sBI + SL[i]*64 + 2*lane);
    }

    // layer-2 constants (HALF 1 only)
    float w2c[4][4], whh2c[4], b2c2[4];
    if (HALF == 1) {
        #pragma unroll
        for (int m = 0; m < 4; ++m) {
            #pragma unroll
            for (int s = 0; s < 4; ++s) {
                int u = s*32 + lane;
                w2c[m][s] = (u < 100) ? W_ih2[m*100 + u] : 0.0f;
            }
            whh2c[m] = W_hh2[m];
            b2c2[m]  = b_ih2[m] + b_hh2[m];
        }
    }

    // cell state: lane owns (unit u = s*16 + lane/2, r = 2*rp + (lane&1)) for rp<3,
    // and (u, r=6) on even lanes for rp==3
    float c1[NS][4];
    #pragma unroll
    for (int i = 0; i < NS; ++i)
        #pragma unroll
        for (int rp = 0; rp < 4; ++rp) c1[i][rp] = 0.0f;
    float h2v = 0.0f, c2v = 0.0f;

    const float* wk_base = sWP + 2*lane;

    float xv[RB], xnx[RB];
    #pragma unroll
    for (int r = 0; r < RB; ++r) {
        int e = base_elem + r;
        xnx[r] = (e < BB) ? input[(long)e*TT + lane] : 0.0f;
    }

    for (int t0 = 0; t0 < TT; t0 += 32) {
        #pragma unroll
        for (int r = 0; r < RB; ++r) xv[r] = xnx[r];
        if (t0 + 32 < TT) {
            #pragma unroll
            for (int r = 0; r < RB; ++r) {
                int e = base_elem + r;
                xnx[r] = (e < BB) ? input[(long)e*TT + t0 + 32 + lane] : 0.0f;
            }
        }

        #pragma unroll 1
        for (int tt = 0; tt < 32; ++tt) {
            // ---- acc init: bias + Wih1*x ----
            ull acc[NS][RB];
            #pragma unroll
            for (int r = 0; r < RB; ++r) {
                float xr = __shfl_sync(0xffffffffu, xv[r], tt);
                ull x2 = pk2(xr, xr);
                #pragma unroll
                for (int i = 0; i < NS; ++i)
                    acc[i][r] = fma2(wxr[i], x2, bbr[i]);
            }

            // ---- hidden matvec over own slots, full k ----
            const float* wkp = wk_base;
            #pragma unroll 2
            for (int kp = 0; kp < 50; ++kp) {
                ull hb0[RB], hb1[RB];
                #pragma unroll
                for (int r = 0; r < RB; ++r) {
                    ulonglong2 hv = *reinterpret_cast<const ulonglong2*>(hd + r*100 + 2*kp);
                    hb0[r] = hv.x; hb1[r] = hv.y;
                }
                #pragma unroll
                for (int i = 0; i < NS; ++i) {
                    ull w0 = *reinterpret_cast<const ull*>(wkp + SL[i]*64);
                    #pragma unroll
                    for (int r = 0; r < RB; ++r)
                        acc[i][r] = fma2(w0, hb0[r], acc[i][r]);
                }
                #pragma unroll
                for (int i = 0; i < NS; ++i) {
                    ull w1 = *reinterpret_cast<const ull*>(wkp + (7 + SL[i])*64);
                    #pragma unroll
                    for (int r = 0; r < RB; ++r)
                        acc[i][r] = fma2(w1, hb1[r], acc[i][r]);
                }
                wkp += 14*64;
            }

            barp(preid);   // all hd[t-1] reads done (both warps) before hd[t] writes

            // ---- activations for own units ----
            const int odd = lane & 1;
            #pragma unroll
            for (int i = 0; i < NS; ++i) {
                const int s = SL[i];
                const bool act = (s < 6) || (lane < 8);
                const int u = s*16 + (lane >> 1);
                #pragma unroll
                for (int rp = 0; rp < 3; ++rp) {
                    float a0, a1, b0, b1;
                    upk2(acc[i][2*rp],   a0, a1);
                    upk2(acc[i][2*rp+1], b0, b1);
                    float xa0 = xor1(a0), xa1 = xor1(a1);
                    float xb0 = xor1(b0), xb1 = xor1(b1);
                    float ii = odd ? xb0 : a0;
                    float gg = odd ? xb1 : a1;
                    float ff = odd ? b0  : xa0;
                    float oo = odd ? b1  : xa1;
                    float c = sigf(ff)*c1[i][rp] + sigf(ii)*tahf(gg);
                    float h = sigf(oo)*tahf(c);
                    if (act) {
                        c1[i][rp] = c;
                        hd[(2*rp + odd)*100 + u] = pk2(h, h);
                    }
                }
                { // rp == 3 -> r = 6, even lanes only
                    float a0, a1;
                    upk2(acc[i][6], a0, a1);
                    float xa0 = xor1(a0), xa1 = xor1(a1);
                    float c = sigf(xa0)*c1[i][3] + sigf(a0)*tahf(a1);
                    float h = sigf(xa1)*tahf(c);
                    if (!odd && act) {
                        c1[i][3] = c;
                        hd[600 + u] = pk2(h, h);
                    }
                }
            }

            barp(postid);  // hd[t] complete before layer-2 / next matvec reads

            // ---- layer 2 (HALF 1) ----
            if (HALF == 1) {
                const float* hdF = reinterpret_cast<const float*>(hd);
                float p4[4][RB];
                #pragma unroll
                for (int m = 0; m < 4; ++m)
                    #pragma unroll
                    for (int r = 0; r < RB; ++r) p4[m][r] = 0.0f;
                #pragma unroll
                for (int s2 = 0; s2 < 4; ++s2) {
                    int u = s2*32 + lane;
                    #pragma unroll
                    for (int r = 0; r < RB; ++r) {
                        float hval = (u < 100) ? hdF[(r*100 + u)*2] : 0.0f;
                        #pragma unroll
                        for (int m = 0; m < 4; ++m)
                            p4[m][r] = fmaf(w2c[m][s2], hval, p4[m][r]);
                    }
                }
                #pragma unroll
                for (int off = 16; off >= 1; off >>= 1)
                    #pragma unroll
                    for (int m = 0; m < 4; ++m)
                        #pragma unroll
                        for (int r = 0; r < RB; ++r)
                            p4[m][r] += __shfl_xor_sync(0xffffffffu, p4[m][r], off);

                float z0 = 0.0f, z1 = 0.0f, z2 = 0.0f, z3 = 0.0f;
                #pragma unroll
                for (int r = 0; r < RB; ++r)
                    if (lane == r) { z0 = p4[0][r]; z1 = p4[1][r]; z2 = p4[2][r]; z3 = p4[3][r]; }

                if (lane < RB) {
                    float i2 = sigf(z0 + whh2c[0]*h2v + b2c2[0]);
                    float f2 = sigf(z1 + whh2c[1]*h2v + b2c2[1]);
                    float g2 = tahf(z2 + whh2c[2]*h2v + b2c2[2]);
                    float o2 = sigf(z3 + whh2c[3]*h2v + b2c2[3]);
                    c2v = f2*c2v + i2*g2;
                    h2v = o2 * tahf(c2v);
                    int e = base_elem + lane;
                    if (e < BB) out[(long)e*TT + t0 + tt] = h2v;
                }
            }
        }
    }
}

__global__ __launch_bounds__(NTHR, 1)
void lstm2_kernel(const float* __restrict__ input,
                  const float* __restrict__ W_ih1,
                  const float* __restrict__ W_hh1,
                  const float* __restrict__ b_ih1,
                  const float* __restrict__ b_hh1,
                  const float* __restrict__ W_ih2,
                  const float* __restrict__ W_hh2,
                  const float* __restrict__ b_ih2,
                  const float* __restrict__ b_hh2,
                  float* __restrict__ out)
{
    extern __shared__ float smem[];
    float* sWP = smem + OFF_WP;
    float* sBI = smem + OFF_BI;
    float* sWX = smem + OFF_WX;

    const int tid = threadIdx.x;

    for (int i = tid; i < SMEM_FLOATS; i += NTHR) smem[i] = 0.0f;
    __syncthreads();

    // pair q (0..199): q=2u -> (i_u, g_u); q=2u+1 -> (f_u, o_u)
    // lo_row = (q&1) ? 100+u : u ; hi_row = lo_row + 200
    for (int i = tid; i < 20000; i += NTHR) {
        int q = i / 100, k = i % 100;
        int u = q >> 1;
        int lo = (q & 1) ? (100 + u) : u;
        int s = q >> 5, l = q & 31;
        sWP[(k*7 + s)*64 + 2*l    ] = W_hh1[lo*100 + k];
        sWP[(k*7 + s)*64 + 2*l + 1] = W_hh1[(lo + 200)*100 + k];
    }
    for (int q = tid; q < 200; q += NTHR) {
        int u = q >> 1;
        int lo = (q & 1) ? (100 + u) : u;
        int hi = lo + 200;
        int s = q >> 5, l = q & 31;
        sBI[s*64 + 2*l    ] = b_ih1[lo] + b_hh1[lo];
        sBI[s*64 + 2*l + 1] = b_ih1[hi] + b_hh1[hi];
        sWX[s*64 + 2*l    ] = W_ih1[lo];
        sWX[s*64 + 2*l + 1] = W_ih1[hi];
    }
    __syncthreads();

    const int warp = tid >> 5, lane = tid & 31;
    const int pair = warp >> 1, half = warp & 1;
    const int base_elem = blockIdx.x * EPC + pair * RB;

    ull* hd = reinterpret_cast<ull*>(smem + OFF_HD) + pair * (RB * 100);

    if (half == 0)
        time_loop<0>(input, out, sWP, sBI, sWX, hd, lane, pair, base_elem,
                     W_ih2, W_hh2, b_ih2, b_hh2);
    else
        time_loop<1>(input, out, sWP, sBI, sWX, hd, lane, pair, base_elem,
                     W_ih2, W_hh2, b_ih2, b_hh2);
}

extern "C" void kernel_launch(void* const* d_in, const int* in_sizes, int n_in,
                              void* d_out, int out_size) {
    const float* input = (const float*)d_in[0];
    const float* W_ih1 = (const float*)d_in[1];
    const float* W_hh1 = (const float*)d_in[2];
    const float* b_ih1 = (const float*)d_in[3];
    const float* b_hh1 = (const float*)d_in[4];
    const float* W_ih2 = (const float*)d_in[5];
    const float* W_hh2 = (const float*)d_in[6];
    const float* b_ih2 = (const float*)d_in[7];
    const float* b_hh2 = (const float*)d_in[8];
    float* out = (float*)d_out;

    cudaFuncSetAttribute(lstm2_kernel, cudaFuncAttributeMaxDynamicSharedMemorySize, SMEM_BYTES);

    const int ctas = (BB + EPC - 1) / EPC;   // 147
    lstm2_kernel<<<ctas, NTHR, SMEM_BYTES>>>(
        input, W_ih1, W_hh1, b_ih1, b_hh1, W_ih2, W_hh2, b_ih2, b_hh2, out);
}

// round 6
// speedup vs baseline: 1.7405x; 1.7405x over previous
#include <cuda_runtime.h>
#include <cstdint>

typedef unsigned long long ull;

#define WARPS 8
#define NTHR (WARPS*32)
#define EPC 28
#define BB 4096
#define TT 2048

// smem float offsets
#define OFF_WP 0                 // [100 k][7 s][64 = 2*lane+half] -> 44800 floats
#define OFF_BI 44800             // [7][64] packed (bsum[p], bsum[p+200])
#define OFF_WX 45248             // [7][64] packed (Wih1[p], Wih1[p+200])
#define OFF_HD 45696             // [WARPS][400 ull] -> 8*800 = 6400 floats
#define SMEM_FLOATS (45696 + 6400)
#define SMEM_BYTES (SMEM_FLOATS*4)

__device__ __forceinline__ ull pk2(float lo, float hi) {
    ull r; asm("mov.b64 %0, {%1, %2};" : "=l"(r) : "f"(lo), "f"(hi)); return r;
}
__device__ __forceinline__ void upk2(ull v, float& lo, float& hi) {
    asm("mov.b64 {%0, %1}, %2;" : "=f"(lo), "=f"(hi) : "l"(v));
}
__device__ __forceinline__ ull fma2(ull a, ull b, ull c) {
    ull d; asm("fma.rn.f32x2 %0, %1, %2, %3;" : "=l"(d) : "l"(a), "l"(b), "l"(c)); return d;
}
__device__ __forceinline__ float sigf(float x) {
    float e = __expf(-x);
    return __fdividef(1.0f, 1.0f + e);
}
__device__ __forceinline__ float tahf(float x) {
    float a = fabsf(x);
    float E = __expf(2.0f * a);
    float t = 1.0f - __fdividef(2.0f, E + 1.0f);
    return (x < 0.0f) ? -t : t;
}

template<int RB>
__device__ __forceinline__ void time_loop(
    const float* __restrict__ input, float* __restrict__ out,
    const float* sWP, const float* sBI, const float* sWX, ull* hd,
    int lane, int base_elem,
    const float* __restrict__ W_ih2, const float* __restrict__ W_hh2,
    const float* __restrict__ b_ih2, const float* __restrict__ b_hh2)
{
    // ---- per-lane cached constants ----
    ull wxr[7], bbr[7];
    #pragma unroll
    for (int s = 0; s < 7; ++s) {
        wxr[s] = *reinterpret_cast<const ull*>(sWX + s*64 + 2*lane);
        bbr[s] = *reinterpret_cast<const ull*>(sBI + s*64 + 2*lane);
    }
    float w2c[4][4];
    #pragma unroll
    for (int m = 0; m < 4; ++m)
        #pragma unroll
        for (int s = 0; s < 4; ++s) {
            int u = s*32 + lane;
            w2c[m][s] = (u < 100) ? W_ih2[m*100 + u] : 0.0f;
        }
    float whh2c[4], b2c2[4];
    #pragma unroll
    for (int m = 0; m < 4; ++m) { whh2c[m] = W_hh2[m]; b2c2[m] = b_ih2[m] + b_hh2[m]; }

    // ---- state ----
    float h1[4][RB], c1[4][RB];
    #pragma unroll
    for (int s = 0; s < 4; ++s)
        #pragma unroll
        for (int r = 0; r < RB; ++r) { h1[s][r] = 0.0f; c1[s][r] = 0.0f; }
    float h2v = 0.0f, c2v = 0.0f;

    const float* wk_base = sWP + 2*lane;

    // prefetch input: lane holds x at time t0+lane for each of its RB elems
    float xv[RB], xnx[RB];
    #pragma unroll
    for (int r = 0; r < RB; ++r) {
        int e = base_elem + r;
        xnx[r] = (e < BB) ? input[(long)e*TT + lane] : 0.0f;
    }

    for (int t0 = 0; t0 < TT; t0 += 32) {
        #pragma unroll
        for (int r = 0; r < RB; ++r) xv[r] = xnx[r];
        if (t0 + 32 < TT) {
            #pragma unroll
            for (int r = 0; r < RB; ++r) {
                int e = base_elem + r;
                xnx[r] = (e < BB) ? input[(long)e*TT + t0 + 32 + lane] : 0.0f;
            }
        }

        #pragma unroll 1
        for (int tt = 0; tt < 32; ++tt) {
            // broadcast x_t, init accumulators: acc = bias + Wih1 * x
            ull acc[7][RB];
            #pragma unroll
            for (int r = 0; r < RB; ++r) {
                float xr = __shfl_sync(0xffffffffu, xv[r], tt);
                ull x2 = pk2(xr, xr);
                #pragma unroll
                for (int s = 0; s < 7; ++s)
                    acc[s][r] = fma2(wxr[s], x2, bbr[s]);
            }

            // hidden matvec over k (h broadcast from warp-private smem)
            const float* wkp = wk_base;
            #pragma unroll 2
            for (int kp = 0; kp < 50; ++kp) {
                ull hb0[RB], hb1[RB];
                #pragma unroll
                for (int r = 0; r < RB; ++r) {
                    ulonglong2 hv = *reinterpret_cast<const ulonglong2*>(hd + r*100 + 2*kp);
                    hb0[r] = hv.x; hb1[r] = hv.y;
                }
                #pragma unroll
                for (int s = 0; s < 7; ++s) {
                    ull w0 = *reinterpret_cast<const ull*>(wkp + s*64);
                    #pragma unroll
                    for (int r = 0; r < RB; ++r)
                        acc[s][r] = fma2(w0, hb0[r], acc[s][r]);
                }
                #pragma unroll
                for (int s = 0; s < 7; ++s) {
                    ull w1 = *reinterpret_cast<const ull*>(wkp + (7+s)*64);
                    #pragma unroll
                    for (int r = 0; r < RB; ++r)
                        acc[s][r] = fma2(w1, hb1[r], acc[s][r]);
                }
                wkp += 14*64;
            }

            // activations: own pair (i_u, g_u) at p=u; partner (f_u, o_u) at p=100+u
            // partner lane = (l+4)&31, register acc[s+3] (l<28) or acc[s+4] (l>=28)
            const int src = (lane + 4) & 31;
            #pragma unroll
            for (int s = 0; s < 3; ++s) {
                #pragma unroll
                for (int r = 0; r < RB; ++r) {
                    float ii, gg; upk2(acc[s][r], ii, gg);
                    float pa0, pa1, pb0, pb1;
                    upk2(acc[s+3][r], pa0, pa1);
                    upk2(acc[s+4][r], pb0, pb1);
                    float fa = __shfl_sync(0xffffffffu, pa0, src);
                    float oa = __shfl_sync(0xffffffffu, pa1, src);
                    float fb = __shfl_sync(0xffffffffu, pb0, src);
                    float ob = __shfl_sync(0xffffffffu, pb1, src);
                    float fv = (lane < 28) ? fa : fb;
                    float ov = (lane < 28) ? oa : ob;
                    float c = sigf(fv)*c1[s][r] + sigf(ii)*tahf(gg);
                    c1[s][r] = c;
                    float h = sigf(ov)*tahf(c);
                    h1[s][r] = h;
                    hd[r*100 + s*32 + lane] = pk2(h, h);
                }
            }
            // s = 3: units 96..99 live on lanes 0..3; partner in acc[6]
            #pragma unroll
            for (int r = 0; r < RB; ++r) {
                float ii, gg; upk2(acc[3][r], ii, gg);
                float pa0, pa1; upk2(acc[6][r], pa0, pa1);
                float fv = __shfl_sync(0xffffffffu, pa0, src);
                float ov = __shfl_sync(0xffffffffu, pa1, src);
                if (lane < 4) {
                    float c = sigf(fv)*c1[3][r] + sigf(ii)*tahf(gg);
                    c1[3][r] = c;
                    float h = sigf(ov)*tahf(c);
                    h1[3][r] = h;
                    hd[r*100 + 96 + lane] = pk2(h, h);
                }
            }
            __syncwarp();

            // layer 2: z[m][r] = sum_u W_ih2[m][u] * h1[u]
            float p[4][RB];
            #pragma unroll
            for (int m = 0; m < 4; ++m)
                #pragma unroll
                for (int r = 0; r < RB; ++r) p[m][r] = 0.0f;
            #pragma unroll
            for (int m = 0; m < 4; ++m)
                #pragma unroll
                for (int s = 0; s < 4; ++s)
                    #pragma unroll
                    for (int r = 0; r < RB; ++r)
                        p[m][r] = fmaf(w2c[m][s], h1[s][r], p[m][r]);
            #pragma unroll
            for (int off = 16; off >= 1; off >>= 1)
                #pragma unroll
                for (int m = 0; m < 4; ++m)
                    #pragma unroll
                    for (int r = 0; r < RB; ++r)
                        p[m][r] += __shfl_xor_sync(0xffffffffu, p[m][r], off);

            // lane r owns element r's scalar LSTM2 state
            float z0 = 0.0f, z1 = 0.0f, z2 = 0.0f, z3 = 0.0f;
            #pragma unroll
            for (int r = 0; r < RB; ++r)
                if (lane == r) { z0 = p[0][r]; z1 = p[1][r]; z2 = p[2][r]; z3 = p[3][r]; }

            if (lane < RB) {
                float i2 = sigf(z0 + whh2c[0]*h2v + b2c2[0]);
                float f2 = sigf(z1 + whh2c[1]*h2v + b2c2[1]);
                float g2 = tahf(z2 + whh2c[2]*h2v + b2c2[2]);
                float o2 = sigf(z3 + whh2c[3]*h2v + b2c2[3]);
                c2v = f2*c2v + i2*g2;
                h2v = o2 * tahf(c2v);
                int e = base_elem + lane;
                if (e < BB) out[(long)e*TT + t0 + tt] = h2v;
            }
        }
    }
}

__global__ __launch_bounds__(NTHR, 1)
void lstm2_kernel(const float* __restrict__ input,
                  const float* __restrict__ W_ih1,
                  const float* __restrict__ W_hh1,
                  const float* __restrict__ b_ih1,
                  const float* __restrict__ b_hh1,
                  const float* __restrict__ W_ih2,
                  const float* __restrict__ W_hh2,
                  const float* __restrict__ b_ih2,
                  const float* __restrict__ b_hh2,
                  float* __restrict__ out)
{
    extern __shared__ float smem[];
    float* sWP = smem + OFF_WP;
    float* sBI = smem + OFF_BI;
    float* sWX = smem + OFF_WX;

    const int tid = threadIdx.x;

    for (int i = tid; i < SMEM_FLOATS; i += NTHR) smem[i] = 0.0f;
    __syncthreads();

    // pair p (0..199): lo = flat row p of W_hh1, hi = flat row p+200.
    //   p = u        -> (i_u, g_u);  p = 100+u -> (f_u, o_u)
    // smem: sWP[(k*7 + s)*64 + 2*l + h], s = p>>5, l = p&31
    for (int i = tid; i < 20000; i += NTHR) {
        int p = i / 100, k = i % 100;
        int s = p >> 5, l = p & 31;
        sWP[(k*7 + s)*64 + 2*l    ] = W_hh1[p*100 + k];
        sWP[(k*7 + s)*64 + 2*l + 1] = W_hh1[(p+200)*100 + k];
    }
    for (int p = tid; p < 200; p += NTHR) {
        int s = p >> 5, l = p & 31;
        sBI[s*64 + 2*l    ] = b_ih1[p]     + b_hh1[p];
        sBI[s*64 + 2*l + 1] = b_ih1[p+200] + b_hh1[p+200];
        sWX[s*64 + 2*l    ] = W_ih1[p];        // W_ih1 is [400,1]
        sWX[s*64 + 2*l + 1] = W_ih1[p+200];
    }
    __syncthreads();

    const int warp = tid >> 5, lane = tid & 31;

    // warps 0-3: RB=4, elems [warp*4, warp*4+4)
    // warps 4-7: RB=3, elems [16 + (warp-4)*3, ...+3)
    ull* hd = reinterpret_cast<ull*>(smem + OFF_HD) + warp * 400;

    if (warp < 4) {
        int base_elem = blockIdx.x * EPC + warp * 4;
        time_loop<4>(input, out, sWP, sBI, sWX, hd, lane, base_elem,
                     W_ih2, W_hh2, b_ih2, b_hh2);
    } else {
        int base_elem = blockIdx.x * EPC + 16 + (warp - 4) * 3;
        time_loop<3>(input, out, sWP, sBI, sWX, hd, lane, base_elem,
                     W_ih2, W_hh2, b_ih2, b_hh2);
    }
}

extern "C" void kernel_launch(void* const* d_in, const int* in_sizes, int n_in,
                              void* d_out, int out_size) {
    const float* input = (const float*)d_in[0];
    const float* W_ih1 = (const float*)d_in[1];
    const float* W_hh1 = (const float*)d_in[2];
    const float* b_ih1 = (const float*)d_in[3];
    const float* b_hh1 = (const float*)d_in[4];
    const float* W_ih2 = (const float*)d_in[5];
    const float* W_hh2 = (const float*)d_in[6];
    const float* b_ih2 = (const float*)d_in[7];
    const float* b_hh2 = (const float*)d_in[8];
    float* out = (float*)d_out;

    cudaFuncSetAttribute(lstm2_kernel, cudaFuncAttributeMaxDynamicSharedMemorySize, SMEM_BYTES);

    const int ctas = (BB + EPC - 1) / EPC;   // 147
    lstm2_kernel<<<ctas, NTHR, SMEM_BYTES>>>(
        input, W_ih1, W_hh1, b_ih1, b_hh1, W_ih2, W_hh2, b_ih2, b_hh2, out);
}